// round 1
// baseline (speedup 1.0000x reference)
#include <cuda_runtime.h>
#include <math.h>

// ---------------- problem constants ----------------
#define HH 480
#define WW2 480
#define HXW (HH*WW2)            // 230400
#define BATCH 8
#define NPIX (BATCH*HXW)        // 1843200
#define NCH 19
#define GRID_P 160              // patches per side
#define NPATCH (BATCH*GRID_P*GRID_P)   // 204800
#define PPB 32                  // patches per block
#define TPB (PPB*9)             // 288 threads

// ---------------- device scratch (no runtime alloc allowed) ----------------
__device__ float  g_semprob[NPIX];
__device__ double g_acc[BATCH][4];      // sum_d, sumsq_d, sum_s, sumsq_s
__device__ double g_gate_acc[3];
__device__ float4 g_norm[BATCH];        // mean_d, rstd_d, mean_s, rstd_s

// ---------------- packed weights ----------------
struct SW {
    float in_w[768];  float in_b[48];     // in_proj  [16,48]
    float out_w[256]; float out_b[16];    // out      [16,16]
    float eg1[256]; float egb1[16]; float eg2[256]; float egb2[16];
    float es1[256]; float esb1[16]; float es2[256]; float esb2[16];
    float ef1[256]; float efb1[16]; float ef2[256]; float efb2[16];
    float gw1[768]; float gb1[16]; float gw2[48]; float gb2[3];   // gate [48,16],[16,3]
    float pw[16];   float pb;                                     // po [16,1]
    float dpw[16]; float dpb[16]; float spw[16]; float spb[16];
    float n1g[16]; float n1b[16]; float n2g[16]; float n2b[16];
};
#define NWFLOATS ((int)(sizeof(SW)/4))   // 3700
__device__ float g_wblob[sizeof(SW)/4];

struct Ptrs { const float* p[32]; };

// dynamic smem layout for moe kernel
#define SK_OFF ((int)sizeof(SW))                 // 14800
#define SV_OFF (SK_OFF + 16*TPB*4)               // +18432
#define SG_OFF (SV_OFF + 16*TPB*4)               // +18432
#define SMEM_TOTAL (SG_OFF + 3*8)                // 51688

// ---------------- pack weights + zero accumulators ----------------
__global__ void pack_kernel(Ptrs in) {
    SW* w = (SW*)g_wblob;
    const int tid = threadIdx.x, nt = blockDim.x;
#define CP(dst, idx, n) for (int i = tid; i < (n); i += nt) (dst)[i] = in.p[idx][i];
    CP(w->in_w, 6, 768)  CP(w->in_b, 7, 48)
    CP(w->out_w, 8, 256) CP(w->out_b, 9, 16)
    CP(w->eg1, 12, 256)  CP(w->egb1, 13, 16) CP(w->eg2, 14, 256) CP(w->egb2, 15, 16)
    CP(w->es1, 16, 256)  CP(w->esb1, 17, 16) CP(w->es2, 18, 256) CP(w->esb2, 19, 16)
    CP(w->ef1, 20, 256)  CP(w->efb1, 21, 16) CP(w->ef2, 22, 256) CP(w->efb2, 23, 16)
    CP(w->gw1, 26, 768)  CP(w->gb1, 27, 16)  CP(w->gw2, 28, 48)  CP(w->gb2, 29, 3)
    CP(w->pw, 30, 16)
    if (tid == 0) w->pb = in.p[31][0];
    CP(w->dpw, 2, 16) CP(w->dpb, 3, 16) CP(w->spw, 4, 16) CP(w->spb, 5, 16)
    CP(w->n1g, 10, 16) CP(w->n1b, 11, 16) CP(w->n2g, 24, 16) CP(w->n2b, 25, 16)
#undef CP
    if (tid < BATCH*4) ((double*)g_acc)[tid] = 0.0;
    if (tid < 3) g_gate_acc[tid] = 0.0;
}

// ---------------- stage 1: sem_prob + per-sample stats ----------------
__global__ void semprob_kernel(const float* __restrict__ sem,
                               const float* __restrict__ depth) {
    const int p = blockIdx.x * 256 + threadIdx.x;   // grid covers NPIX exactly
    const int b = p / HXW;
    const int ip = p - b * HXW;
    const float* base = sem + (long)b * NCH * HXW + ip;
    float v[NCH];
#pragma unroll
    for (int c = 0; c < NCH; c++) v[c] = __ldg(base + (long)c * HXW);
    float mx = v[0];
#pragma unroll
    for (int c = 1; c < NCH; c++) mx = fmaxf(mx, v[c]);
    float sum = 0.f;
#pragma unroll
    for (int c = 0; c < NCH; c++) sum += expf(v[c] - mx);
    const float prob = 1.0f / sum;          // max of softmax = exp(mx - lse)
    g_semprob[p] = prob;
    const float d = depth[p];

    double rd = (double)d, rd2 = (double)d * d;
    double rs = (double)prob, rs2 = (double)prob * prob;
#pragma unroll
    for (int off = 16; off > 0; off >>= 1) {
        rd  += __shfl_down_sync(0xffffffffu, rd,  off);
        rd2 += __shfl_down_sync(0xffffffffu, rd2, off);
        rs  += __shfl_down_sync(0xffffffffu, rs,  off);
        rs2 += __shfl_down_sync(0xffffffffu, rs2, off);
    }
    __shared__ double sp[8][4];
    const int lane = threadIdx.x & 31, wid = threadIdx.x >> 5;
    if (lane == 0) { sp[wid][0] = rd; sp[wid][1] = rd2; sp[wid][2] = rs; sp[wid][3] = rs2; }
    __syncthreads();
    if (threadIdx.x == 0) {
        double a0 = 0, a1 = 0, a2 = 0, a3 = 0;
        for (int i = 0; i < 8; i++) { a0 += sp[i][0]; a1 += sp[i][1]; a2 += sp[i][2]; a3 += sp[i][3]; }
        atomicAdd(&g_acc[b][0], a0); atomicAdd(&g_acc[b][1], a1);
        atomicAdd(&g_acc[b][2], a2); atomicAdd(&g_acc[b][3], a3);
    }
}

__global__ void finalize_kernel() {
    const int b = threadIdx.x;
    if (b < BATCH) {
        const double n = (double)HXW;
        double md = g_acc[b][0] / n;
        double vd = (g_acc[b][1] - n * md * md) / (n - 1.0);
        double ms = g_acc[b][2] / n;
        double vs = (g_acc[b][3] - n * ms * ms) / (n - 1.0);
        g_norm[b] = make_float4((float)md, (float)(1.0 / (sqrt(vd) + 1e-6)),
                                (float)ms, (float)(1.0 / (sqrt(vs) + 1e-6)));
    }
}

// ---------------- stage 2 helpers ----------------
__device__ __forceinline__ void ln16(float* x, const float* g, const float* b) {
    float m = 0.f;
#pragma unroll
    for (int j = 0; j < 16; j++) m += x[j];
    m *= 0.0625f;
    float v = 0.f;
#pragma unroll
    for (int j = 0; j < 16; j++) { float d = x[j] - m; v = fmaf(d, d, v); }
    v *= 0.0625f;
    const float r = rsqrtf(v + 1e-5f);
#pragma unroll
    for (int j = 0; j < 16; j++) x[j] = (x[j] - m) * r * g[j] + b[j];
}

__device__ __forceinline__ float gelu_exact(float x) {
    return 0.5f * x * (1.0f + erff(x * 0.70710678118654752f));
}

__device__ __forceinline__ void expert16(const float* in, const float* w1, const float* b1,
                                         const float* w2, const float* b2, float* o) {
    float h[16];
#pragma unroll
    for (int j = 0; j < 16; j++) h[j] = b1[j];
#pragma unroll
    for (int k = 0; k < 16; k++) {
        const float v = in[k]; const float* r = &w1[k * 16];
#pragma unroll
        for (int j = 0; j < 16; j++) h[j] = fmaf(v, r[j], h[j]);
    }
#pragma unroll
    for (int j = 0; j < 16; j++) h[j] = gelu_exact(h[j]);
#pragma unroll
    for (int j = 0; j < 16; j++) o[j] = in[j] + b2[j];
#pragma unroll
    for (int k = 0; k < 16; k++) {
        const float v = h[k]; const float* r = &w2[k * 16];
#pragma unroll
        for (int j = 0; j < 16; j++) o[j] = fmaf(v, r[j], o[j]);
    }
}

// ---------------- stage 2: per-patch transformer/MoE ----------------
__global__ void __launch_bounds__(TPB, 2)
moe_kernel(const float* __restrict__ depth, float* __restrict__ out) {
    extern __shared__ unsigned char dsm[];
    SW& w = *(SW*)dsm;
    float (*s_k)[TPB] = (float (*)[TPB])(dsm + SK_OFF);
    float (*s_v)[TPB] = (float (*)[TPB])(dsm + SV_OFF);
    double* s_gate = (double*)(dsm + SG_OFF);

    const int tid = threadIdx.x;
    for (int i = tid; i < NWFLOATS; i += TPB) ((float*)&w)[i] = g_wblob[i];
    if (tid < 3) s_gate[tid] = 0.0;
    __syncthreads();

    const int pl = tid / 9;            // patch within block
    const int t = tid - pl * 9;        // token 0..8
    const int P = blockIdx.x * PPB + pl;
    const int b = P / (GRID_P * GRID_P);
    const int rem = P - b * (GRID_P * GRID_P);
    const int hh = rem / GRID_P, ww = rem - hh * GRID_P;
    const int py = hh * 3 + t / 3, px = ww * 3 + (t % 3);
    const int pix = (b * HH + py) * WW2 + px;

    const float4 nm = g_norm[b];
    const float dn = (depth[pix] - nm.x) * nm.y;
    const float sn = (g_semprob[pix] - nm.z) * nm.w;

    float x[16];
#pragma unroll
    for (int j = 0; j < 16; j++)
        x[j] = fmaf(dn, w.dpw[j], w.dpb[j]) + fmaf(sn, w.spw[j], w.spb[j]);
    ln16(x, w.n1g, w.n1b);

    // qkv
    float q[16];
    {
        float kk[16], vv[16];
#pragma unroll
        for (int j = 0; j < 16; j++) { q[j] = w.in_b[j]; kk[j] = w.in_b[16 + j]; vv[j] = w.in_b[32 + j]; }
#pragma unroll
        for (int k = 0; k < 16; k++) {
            const float xv = x[k]; const float* r = &w.in_w[k * 48];
#pragma unroll
            for (int j = 0; j < 16; j++) {
                q[j]  = fmaf(xv, r[j],      q[j]);
                kk[j] = fmaf(xv, r[16 + j], kk[j]);
                vv[j] = fmaf(xv, r[32 + j], vv[j]);
            }
        }
#pragma unroll
        for (int j = 0; j < 16; j++) { s_k[j][tid] = kk[j]; s_v[j][tid] = vv[j]; }
    }
    __syncthreads();

    const int pb = tid - t;     // first thread of this patch
    float ao[16];
#pragma unroll
    for (int h = 0; h < 2; h++) {
        float sc[9]; float mx = -1e30f;
#pragma unroll
        for (int tt = 0; tt < 9; tt++) {
            float a = 0.f;
#pragma unroll
            for (int d8 = 0; d8 < 8; d8++) a = fmaf(q[h * 8 + d8], s_k[h * 8 + d8][pb + tt], a);
            a *= 0.35355339059327373f;   // 1/sqrt(8)
            sc[tt] = a; mx = fmaxf(mx, a);
        }
        float sum = 0.f;
#pragma unroll
        for (int tt = 0; tt < 9; tt++) { sc[tt] = expf(sc[tt] - mx); sum += sc[tt]; }
        const float inv = 1.0f / sum;
#pragma unroll
        for (int d8 = 0; d8 < 8; d8++) {
            float acc = 0.f;
#pragma unroll
            for (int tt = 0; tt < 9; tt++) acc = fmaf(sc[tt], s_v[h * 8 + d8][pb + tt], acc);
            ao[h * 8 + d8] = acc * inv;
        }
    }
    // out projection + residual + LN (n1 reused)
    {
        float o[16];
#pragma unroll
        for (int j = 0; j < 16; j++) o[j] = w.out_b[j];
#pragma unroll
        for (int k = 0; k < 16; k++) {
            const float v = ao[k]; const float* r = &w.out_w[k * 16];
#pragma unroll
            for (int j = 0; j < 16; j++) o[j] = fmaf(v, r[j], o[j]);
        }
#pragma unroll
        for (int j = 0; j < 16; j++) x[j] += o[j];
    }
    ln16(x, w.n1g, w.n1b);

    __syncthreads();                       // attention reads done; reuse s_k for x
#pragma unroll
    for (int j = 0; j < 16; j++) s_k[j][tid] = x[j];
    __syncthreads();

    // gate (computed redundantly per token thread — identical result per patch)
    float g0, g1, g2;
    {
        float hid[16];
#pragma unroll
        for (int i = 0; i < 16; i++) hid[i] = w.gb1[i];
#pragma unroll
        for (int j = 0; j < 16; j++) {
            float vals[9]; float m = 0.f, mx = -1e30f;
#pragma unroll
            for (int tt = 0; tt < 9; tt++) {
                const float v = s_k[j][pb + tt];
                vals[tt] = v; m += v; mx = fmaxf(mx, v);
            }
            m *= (1.0f / 9.0f);
            float var = 0.f;
#pragma unroll
            for (int tt = 0; tt < 9; tt++) { const float d = vals[tt] - m; var = fmaf(d, d, var); }
            const float sd = sqrtf(var * (1.0f / 8.0f));   // ddof=1
            const float* r0 = &w.gw1[j * 16];
            const float* r1 = &w.gw1[(16 + j) * 16];
            const float* r2 = &w.gw1[(32 + j) * 16];
#pragma unroll
            for (int i = 0; i < 16; i++)
                hid[i] += m * r0[i] + mx * r1[i] + sd * r2[i];
        }
        float lg0 = w.gb2[0], lg1 = w.gb2[1], lg2 = w.gb2[2];
#pragma unroll
        for (int i = 0; i < 16; i++) {
            const float hv = gelu_exact(hid[i]);
            lg0 = fmaf(hv, w.gw2[i * 3 + 0], lg0);
            lg1 = fmaf(hv, w.gw2[i * 3 + 1], lg1);
            lg2 = fmaf(hv, w.gw2[i * 3 + 2], lg2);
        }
        const float mx = fmaxf(lg0, fmaxf(lg1, lg2));
        const float e0 = expf(lg0 - mx), e1 = expf(lg1 - mx), e2 = expf(lg2 - mx);
        const float inv = 1.0f / (e0 + e1 + e2);
        g0 = e0 * inv; g1 = e1 * inv; g2 = e2 * inv;
    }
    if (t == 0) {
        atomicAdd(&s_gate[0], (double)g0);
        atomicAdd(&s_gate[1], (double)g1);
        atomicAdd(&s_gate[2], (double)g2);
    }

    // experts + moe combine
    float tin[16], o[16], moe[16];
#pragma unroll
    for (int j = 0; j < 16; j++) tin[j] = x[j] + fmaf(dn, w.dpw[j], w.dpb[j]);
    expert16(tin, w.eg1, w.egb1, w.eg2, w.egb2, o);
#pragma unroll
    for (int j = 0; j < 16; j++) moe[j] = g0 * o[j];
#pragma unroll
    for (int j = 0; j < 16; j++) tin[j] = x[j] + fmaf(sn, w.spw[j], w.spb[j]);
    expert16(tin, w.es1, w.esb1, w.es2, w.esb2, o);
#pragma unroll
    for (int j = 0; j < 16; j++) moe[j] = fmaf(g1, o[j], moe[j]);
#pragma unroll
    for (int j = 0; j < 16; j++)
        tin[j] = x[j] + fmaf(dn, w.dpw[j], w.dpb[j]) + fmaf(sn, w.spw[j], w.spb[j]);
    expert16(tin, w.ef1, w.efb1, w.ef2, w.efb2, o);
#pragma unroll
    for (int j = 0; j < 16; j++) moe[j] = fmaf(g2, o[j], moe[j]);

#pragma unroll
    for (int j = 0; j < 16; j++) moe[j] += x[j];
    ln16(moe, w.n2g, w.n2b);
    float z = w.pb;
#pragma unroll
    for (int j = 0; j < 16; j++) z = fmaf(moe[j], w.pw[j], z);
    out[pix] = 1.0f / (1.0f + expf(-z));

    __syncthreads();
    if (tid < 3) atomicAdd(&g_gate_acc[tid], s_gate[tid]);
}

__global__ void tail_kernel(float* __restrict__ out) {
    if (threadIdx.x < 3)
        out[NPIX + threadIdx.x] = (float)(g_gate_acc[threadIdx.x] / (double)NPATCH);
}

// ---------------- launch ----------------
extern "C" void kernel_launch(void* const* d_in, const int* in_sizes, int n_in,
                              void* d_out, int out_size) {
    Ptrs ptrs;
    for (int i = 0; i < 32; i++) ptrs.p[i] = (const float*)d_in[i];
    const float* depth = (const float*)d_in[0];
    const float* sem   = (const float*)d_in[1];
    float* out = (float*)d_out;

    cudaFuncSetAttribute(moe_kernel, cudaFuncAttributeMaxDynamicSharedMemorySize, SMEM_TOTAL);

    pack_kernel<<<1, 256>>>(ptrs);
    semprob_kernel<<<NPIX / 256, 256>>>(sem, depth);
    finalize_kernel<<<1, 32>>>();
    moe_kernel<<<NPATCH / PPB, TPB, SMEM_TOTAL>>>(depth, out);
    tail_kernel<<<1, 32>>>(out);
}

// round 2
// speedup vs baseline: 1.2205x; 1.2205x over previous
#include <cuda_runtime.h>
#include <math.h>

// ---------------- problem constants ----------------
#define HH 480
#define WW2 480
#define HXW (HH*WW2)            // 230400
#define BATCH 8
#define NPIX (BATCH*HXW)        // 1843200
#define NCH 19
#define GRID_P 160              // patches per side
#define NPATCH (BATCH*GRID_P*GRID_P)   // 204800
#define PPB 32                  // patches per block
#define TPB (PPB*9)             // 288 threads
#define KSTR 18                 // smem row stride (floats) for K/V/X rows

typedef unsigned long long ull;

// ---------------- f32x2 helpers (Blackwell FFMA2) ----------------
__device__ __forceinline__ ull pk2(float a, float b) {
    ull r; asm("mov.b64 %0, {%1,%2};" : "=l"(r) : "f"(a), "f"(b)); return r;
}
__device__ __forceinline__ ull dup2(float a) {
    ull r; asm("mov.b64 %0, {%1,%1};" : "=l"(r) : "f"(a)); return r;
}
__device__ __forceinline__ void upk2(ull v, float& a, float& b) {
    asm("mov.b64 {%0,%1}, %2;" : "=f"(a), "=f"(b) : "l"(v));
}
__device__ __forceinline__ ull fma2(ull a, ull b, ull c) {
    ull d; asm("fma.rn.f32x2 %0, %1, %2, %3;" : "=l"(d) : "l"(a), "l"(b), "l"(c)); return d;
}

// ---------------- device scratch ----------------
__device__ float  g_semprob[NPIX];
__device__ double g_acc[BATCH][4];
__device__ double g_gate_acc[3];
__device__ float4 g_norm[BATCH];

// ---------------- packed weights (all matmul arrays 16B-aligned) ----------------
struct SW {
    float in_w[768];  float in_b[48];
    float out_w[256]; float out_b[16];
    float eg1[256]; float egb1[16]; float eg2[256]; float egb2[16];
    float es1[256]; float esb1[16]; float es2[256]; float esb2[16];
    float ef1[256]; float efb1[16]; float ef2[256]; float efb2[16];
    float gw1t[768]; float gb1[16];     // g_w1 transposed to [16][48]
    float gw2[48];  float gb2[4];       // padded
    float pw[16];   float pb[4];        // padded
    float dpw[16]; float dpb[16]; float spw[16]; float spb[16];
    float n1g[16]; float n1b[16]; float n2g[16]; float n2b[16];
};
#define NWFLOATS ((int)(sizeof(SW)/4))
__device__ float g_wblob[sizeof(SW)/4];

struct Ptrs { const float* p[32]; };

// dynamic smem layout
#define SW_BYTES ((int)sizeof(SW))
#define SK_OFF  SW_BYTES
#define SK_BYTES (TPB*KSTR*4)
#define SV_OFF  (SK_OFF + SK_BYTES)
#define SV_BYTES (TPB*KSTR*4)
// overlays (valid after attention completes):
#define SX_OFF    SK_OFF                     // x rows [tid][KSTR]
#define SSTAT_OFF SV_OFF                     // [32][48] gate stats
#define SHID_OFF  (SSTAT_OFF + 32*48*4)      // [32][16] gate hidden
#define SGATE_OFF (SV_OFF + SV_BYTES)
#define SMEM_TOTAL (SGATE_OFF + 32)

// ---------------- pack weights + zero accumulators ----------------
__global__ void pack_kernel(Ptrs in) {
    SW* w = (SW*)g_wblob;
    const int tid = threadIdx.x, nt = blockDim.x;
#define CP(dst, idx, n) for (int i = tid; i < (n); i += nt) (dst)[i] = in.p[idx][i];
    CP(w->in_w, 6, 768)  CP(w->in_b, 7, 48)
    CP(w->out_w, 8, 256) CP(w->out_b, 9, 16)
    CP(w->eg1, 12, 256)  CP(w->egb1, 13, 16) CP(w->eg2, 14, 256) CP(w->egb2, 15, 16)
    CP(w->es1, 16, 256)  CP(w->esb1, 17, 16) CP(w->es2, 18, 256) CP(w->esb2, 19, 16)
    CP(w->ef1, 20, 256)  CP(w->efb1, 21, 16) CP(w->ef2, 22, 256) CP(w->efb2, 23, 16)
    CP(w->gb1, 27, 16)   CP(w->gw2, 28, 48)  CP(w->pw, 30, 16)
    CP(w->dpw, 2, 16) CP(w->dpb, 3, 16) CP(w->spw, 4, 16) CP(w->spb, 5, 16)
    CP(w->n1g, 10, 16) CP(w->n1b, 11, 16) CP(w->n2g, 24, 16) CP(w->n2b, 25, 16)
#undef CP
    // transpose g_w1 [48,16] -> gw1t [16][48]
    for (int i = tid; i < 768; i += nt) {
        int r = i / 48, s = i - r * 48;
        w->gw1t[i] = in.p[26][s * 16 + r];
    }
    if (tid < 3) w->gb2[tid] = in.p[29][tid];
    if (tid == 3) w->gb2[3] = 0.f;
    if (tid == 0) { w->pb[0] = in.p[31][0]; }
    if (tid < BATCH*4) ((double*)g_acc)[tid] = 0.0;
    if (tid < 3) g_gate_acc[tid] = 0.0;
}

// ---------------- stage 1: sem_prob + per-sample stats (float4) ----------------
__global__ void semprob_kernel(const float* __restrict__ sem,
                               const float* __restrict__ depth) {
    const int q = blockIdx.x * 256 + threadIdx.x;   // one float4 per thread
    const int p4 = q * 4;
    const int b = p4 / HXW;
    const int ip = p4 - b * HXW;
    const float4* base = (const float4*)(sem + (long)b * NCH * HXW + ip);
    float4 v[NCH];
#pragma unroll
    for (int c = 0; c < NCH; c++) v[c] = __ldg(base + (long)c * (HXW/4));
    float4 mx = v[0];
#pragma unroll
    for (int c = 1; c < NCH; c++) {
        mx.x = fmaxf(mx.x, v[c].x); mx.y = fmaxf(mx.y, v[c].y);
        mx.z = fmaxf(mx.z, v[c].z); mx.w = fmaxf(mx.w, v[c].w);
    }
    float4 sum = make_float4(0.f, 0.f, 0.f, 0.f);
#pragma unroll
    for (int c = 0; c < NCH; c++) {
        sum.x += __expf(v[c].x - mx.x); sum.y += __expf(v[c].y - mx.y);
        sum.z += __expf(v[c].z - mx.z); sum.w += __expf(v[c].w - mx.w);
    }
    float4 prob;
    prob.x = __fdividef(1.0f, sum.x); prob.y = __fdividef(1.0f, sum.y);
    prob.z = __fdividef(1.0f, sum.z); prob.w = __fdividef(1.0f, sum.w);
    ((float4*)g_semprob)[q] = prob;
    const float4 d = __ldg((const float4*)depth + q);

    double rd  = (double)d.x + (double)d.y + (double)d.z + (double)d.w;
    double rd2 = (double)d.x*d.x + (double)d.y*d.y + (double)d.z*d.z + (double)d.w*d.w;
    double rs  = (double)prob.x + (double)prob.y + (double)prob.z + (double)prob.w;
    double rs2 = (double)prob.x*prob.x + (double)prob.y*prob.y
               + (double)prob.z*prob.z + (double)prob.w*prob.w;
#pragma unroll
    for (int off = 16; off > 0; off >>= 1) {
        rd  += __shfl_down_sync(0xffffffffu, rd,  off);
        rd2 += __shfl_down_sync(0xffffffffu, rd2, off);
        rs  += __shfl_down_sync(0xffffffffu, rs,  off);
        rs2 += __shfl_down_sync(0xffffffffu, rs2, off);
    }
    __shared__ double sp[8][4];
    const int lane = threadIdx.x & 31, wid = threadIdx.x >> 5;
    if (lane == 0) { sp[wid][0] = rd; sp[wid][1] = rd2; sp[wid][2] = rs; sp[wid][3] = rs2; }
    __syncthreads();
    if (threadIdx.x == 0) {
        double a0 = 0, a1 = 0, a2 = 0, a3 = 0;
        for (int i = 0; i < 8; i++) { a0 += sp[i][0]; a1 += sp[i][1]; a2 += sp[i][2]; a3 += sp[i][3]; }
        atomicAdd(&g_acc[b][0], a0); atomicAdd(&g_acc[b][1], a1);
        atomicAdd(&g_acc[b][2], a2); atomicAdd(&g_acc[b][3], a3);
    }
}

__global__ void finalize_kernel() {
    const int b = threadIdx.x;
    if (b < BATCH) {
        const double n = (double)HXW;
        double md = g_acc[b][0] / n;
        double vd = (g_acc[b][1] - n * md * md) / (n - 1.0);
        double ms = g_acc[b][2] / n;
        double vs = (g_acc[b][3] - n * ms * ms) / (n - 1.0);
        g_norm[b] = make_float4((float)md, (float)(1.0 / (sqrt(vd) + 1e-6)),
                                (float)ms, (float)(1.0 / (sqrt(vs) + 1e-6)));
    }
}

// ---------------- stage 2 helpers ----------------
__device__ __forceinline__ void ln16(float* x, const float* g, const float* b) {
    float m = 0.f;
#pragma unroll
    for (int j = 0; j < 16; j++) m += x[j];
    m *= 0.0625f;
    float v = 0.f;
#pragma unroll
    for (int j = 0; j < 16; j++) { float d = x[j] - m; v = fmaf(d, d, v); }
    v *= 0.0625f;
    const float r = rsqrtf(v + 1e-5f);
#pragma unroll
    for (int j = 0; j < 16; j++) x[j] = (x[j] - m) * r * g[j] + b[j];
}

// branchless gelu: A&S 7.1.26 erf (|eps| <= 1.5e-7)
__device__ __forceinline__ float gelu_fast(float x) {
    const float u = 0.70710678118654752f * x;
    const float a = fabsf(u);
    const float t = __fdividef(1.0f, fmaf(0.3275911f, a, 1.0f));
    float p =              1.061405429f;
    p = fmaf(p, t, -1.453152027f);
    p = fmaf(p, t,  1.421413741f);
    p = fmaf(p, t, -0.284496736f);
    p = fmaf(p, t,  0.254829592f);
    p = p * t;
    const float e = __expf(-u * u);
    float erf_u = 1.0f - p * e;         // erf(|u|)
    erf_u = copysignf(erf_u, u);
    return 0.5f * x * (1.0f + erf_u);
}

// out = bias + in @ W   (W [16][16] row-major in smem, FFMA2)
__device__ __forceinline__ void mm16(const float* in, const float* wm,
                                     const float* bias, float* out) {
    ull acc[8];
    const ull* bp = (const ull*)bias;
#pragma unroll
    for (int p = 0; p < 8; p++) acc[p] = bp[p];
#pragma unroll
    for (int k = 0; k < 16; k++) {
        const ull xv = dup2(in[k]);
        const ull* r = (const ull*)&wm[k * 16];
#pragma unroll
        for (int p = 0; p < 8; p++) acc[p] = fma2(xv, r[p], acc[p]);
    }
#pragma unroll
    for (int p = 0; p < 8; p++) upk2(acc[p], out[2*p], out[2*p+1]);
}

__device__ __forceinline__ void expert16(const float* in, const float* w1, const float* b1,
                                         const float* w2, const float* b2, float* o) {
    float h[16];
    mm16(in, w1, b1, h);
#pragma unroll
    for (int j = 0; j < 16; j++) h[j] = gelu_fast(h[j]);
    mm16(h, w2, b2, o);
#pragma unroll
    for (int j = 0; j < 16; j++) o[j] += in[j];
}

// ---------------- stage 2: per-patch transformer/MoE ----------------
__global__ void __launch_bounds__(TPB, 2)
moe_kernel(const float* __restrict__ depth, float* __restrict__ out) {
    extern __shared__ __align__(16) unsigned char dsm[];
    SW& w = *(SW*)dsm;
    float* s_k = (float*)(dsm + SK_OFF);      // [TPB][KSTR]
    float* s_v = (float*)(dsm + SV_OFF);      // [TPB][KSTR]
    float* s_x = (float*)(dsm + SX_OFF);      // overlay on s_k
    float* s_st = (float*)(dsm + SSTAT_OFF);  // [32][48] overlay on s_v
    float* s_hid = (float*)(dsm + SHID_OFF);  // [32][16]
    double* s_gate = (double*)(dsm + SGATE_OFF);

    const int tid = threadIdx.x;
    for (int i = tid; i < NWFLOATS; i += TPB) ((float*)&w)[i] = g_wblob[i];
    if (tid < 3) s_gate[tid] = 0.0;
    __syncthreads();                                         // S0

    const int pl = tid / 9;
    const int t = tid - pl * 9;
    const int P = blockIdx.x * PPB + pl;
    const int b = P / (GRID_P * GRID_P);
    const int rem = P - b * (GRID_P * GRID_P);
    const int hh = rem / GRID_P, ww = rem - hh * GRID_P;
    const int py = hh * 3 + t / 3, px = ww * 3 + (t % 3);
    const int pix = (b * HH + py) * WW2 + px;
    const int pb = tid - t;                                  // first thread of patch

    const float4 nm = g_norm[b];
    const float dn = (depth[pix] - nm.x) * nm.y;
    const float sn = (g_semprob[pix] - nm.z) * nm.w;

    float x[16];
#pragma unroll
    for (int j = 0; j < 16; j++)
        x[j] = fmaf(dn, w.dpw[j], w.dpb[j]) + fmaf(sn, w.spw[j], w.spb[j]);
    ln16(x, w.n1g, w.n1b);

    // ---- qkv (q kept packed for attention) ----
    ull aq[8];
    {
        ull ak[8], av[8];
        const ull* bp = (const ull*)w.in_b;
#pragma unroll
        for (int p = 0; p < 8; p++) { aq[p] = bp[p]; ak[p] = bp[8+p]; av[p] = bp[16+p]; }
#pragma unroll
        for (int k = 0; k < 16; k++) {
            const ull xv = dup2(x[k]);
            const ull* r = (const ull*)&w.in_w[k * 48];
#pragma unroll
            for (int p = 0; p < 8; p++) aq[p] = fma2(xv, r[p],    aq[p]);
#pragma unroll
            for (int p = 0; p < 8; p++) ak[p] = fma2(xv, r[8+p],  ak[p]);
#pragma unroll
            for (int p = 0; p < 8; p++) av[p] = fma2(xv, r[16+p], av[p]);
        }
        ull* krow = (ull*)&s_k[tid * KSTR];
        ull* vrow = (ull*)&s_v[tid * KSTR];
#pragma unroll
        for (int p = 0; p < 8; p++) { krow[p] = ak[p]; vrow[p] = av[p]; }
    }
    __syncthreads();                                         // S1

    // ---- attention ----
    float ao[16];
#pragma unroll
    for (int h = 0; h < 2; h++) {
        float sc[9]; float mx = -1e30f;
#pragma unroll
        for (int tt = 0; tt < 9; tt++) {
            const ull* kr = (const ull*)&s_k[(pb + tt) * KSTR];
            ull acc = 0ull;
#pragma unroll
            for (int p = 0; p < 4; p++) acc = fma2(aq[h*4 + p], kr[h*4 + p], acc);
            float a0, a1; upk2(acc, a0, a1);
            const float s = (a0 + a1) * 0.35355339059327373f;
            sc[tt] = s; mx = fmaxf(mx, s);
        }
        float sum = 0.f;
#pragma unroll
        for (int tt = 0; tt < 9; tt++) { sc[tt] = __expf(sc[tt] - mx); sum += sc[tt]; }
        const float inv = __fdividef(1.0f, sum);
        ull vacc[4] = {0ull, 0ull, 0ull, 0ull};
#pragma unroll
        for (int tt = 0; tt < 9; tt++) {
            const ull s2 = dup2(sc[tt]);
            const ull* vr = (const ull*)&s_v[(pb + tt) * KSTR];
#pragma unroll
            for (int p = 0; p < 4; p++) vacc[p] = fma2(s2, vr[h*4 + p], vacc[p]);
        }
#pragma unroll
        for (int p = 0; p < 4; p++) {
            float a0, a1; upk2(vacc[p], a0, a1);
            ao[h*8 + 2*p] = a0 * inv; ao[h*8 + 2*p + 1] = a1 * inv;
        }
    }
    // out projection + residual + LN (n1 reused)
    {
        float o[16];
        mm16(ao, w.out_w, w.out_b, o);
#pragma unroll
        for (int j = 0; j < 16; j++) x[j] += o[j];
    }
    ln16(x, w.n1g, w.n1b);

    __syncthreads();                                         // S2: attn reads done
#pragma unroll
    for (int j = 0; j < 16; j++) s_x[tid * KSTR + j] = x[j];
    __syncthreads();                                         // S3

    // ---- gate: cooperative stats (each thread 1-2 channels) ----
#pragma unroll
    for (int cc = 0; cc < 2; cc++) {
        const int j = (cc == 0) ? t : (9 + t);
        if (cc == 0 || t < 7) {
            float vals[9]; float m = 0.f, mxv = -1e30f;
#pragma unroll
            for (int tt = 0; tt < 9; tt++) {
                const float v = s_x[(pb + tt) * KSTR + j];
                vals[tt] = v; m += v; mxv = fmaxf(mxv, v);
            }
            m *= (1.0f / 9.0f);
            float var = 0.f;
#pragma unroll
            for (int tt = 0; tt < 9; tt++) { const float d = vals[tt] - m; var = fmaf(d, d, var); }
            const float sd = sqrtf(var * 0.125f);            // ddof=1
            float* st = &s_st[pl * 48];
            st[j] = m; st[16 + j] = mxv; st[32 + j] = sd;
        }
    }
    __syncthreads();                                         // S4

    // hid: thread t<8 computes outputs t and 8+t
    if (t < 8) {
        const ull* stp = (const ull*)&s_st[pl * 48];
#pragma unroll
        for (int cc = 0; cc < 2; cc++) {
            const int i = (cc == 0) ? t : (8 + t);
            const ull* wr = (const ull*)&w.gw1t[i * 48];
            ull acc = 0ull;
#pragma unroll
            for (int p = 0; p < 24; p++) acc = fma2(stp[p], wr[p], acc);
            float a0, a1; upk2(acc, a0, a1);
            s_hid[pl * 16 + i] = gelu_fast(a0 + a1 + w.gb1[i]);
        }
    }
    __syncthreads();                                         // S5

    // logits + softmax (redundant per thread, cheap)
    float g0, g1, g2;
    {
        float lg0 = w.gb2[0], lg1 = w.gb2[1], lg2 = w.gb2[2];
        const float* hv = &s_hid[pl * 16];
#pragma unroll
        for (int i = 0; i < 16; i++) {
            const float h = hv[i];
            lg0 = fmaf(h, w.gw2[i*3 + 0], lg0);
            lg1 = fmaf(h, w.gw2[i*3 + 1], lg1);
            lg2 = fmaf(h, w.gw2[i*3 + 2], lg2);
        }
        const float mxl = fmaxf(lg0, fmaxf(lg1, lg2));
        const float e0 = __expf(lg0 - mxl), e1 = __expf(lg1 - mxl), e2 = __expf(lg2 - mxl);
        const float inv = __fdividef(1.0f, e0 + e1 + e2);
        g0 = e0 * inv; g1 = e1 * inv; g2 = e2 * inv;
    }
    if (t == 0) {
        atomicAdd(&s_gate[0], (double)g0);
        atomicAdd(&s_gate[1], (double)g1);
        atomicAdd(&s_gate[2], (double)g2);
    }

    // ---- experts + moe combine ----
    float tin[16], o[16], moe[16];
#pragma unroll
    for (int j = 0; j < 16; j++) tin[j] = x[j] + fmaf(dn, w.dpw[j], w.dpb[j]);
    expert16(tin, w.eg1, w.egb1, w.eg2, w.egb2, o);
#pragma unroll
    for (int j = 0; j < 16; j++) moe[j] = g0 * o[j];
#pragma unroll
    for (int j = 0; j < 16; j++) tin[j] = x[j] + fmaf(sn, w.spw[j], w.spb[j]);
    expert16(tin, w.es1, w.esb1, w.es2, w.esb2, o);
#pragma unroll
    for (int j = 0; j < 16; j++) moe[j] = fmaf(g1, o[j], moe[j]);
#pragma unroll
    for (int j = 0; j < 16; j++)
        tin[j] = x[j] + fmaf(dn, w.dpw[j], w.dpb[j]) + fmaf(sn, w.spw[j], w.spb[j]);
    expert16(tin, w.ef1, w.efb1, w.ef2, w.efb2, o);
#pragma unroll
    for (int j = 0; j < 16; j++) moe[j] = fmaf(g2, o[j], moe[j]);

#pragma unroll
    for (int j = 0; j < 16; j++) moe[j] += x[j];
    ln16(moe, w.n2g, w.n2b);
    float z = w.pb[0];
#pragma unroll
    for (int j = 0; j < 16; j++) z = fmaf(moe[j], w.pw[j], z);
    out[pix] = __fdividef(1.0f, 1.0f + __expf(-z));

    __syncthreads();                                         // S6
    if (tid < 3) atomicAdd(&g_gate_acc[tid], s_gate[tid]);
}

__global__ void tail_kernel(float* __restrict__ out) {
    if (threadIdx.x < 3)
        out[NPIX + threadIdx.x] = (float)(g_gate_acc[threadIdx.x] / (double)NPATCH);
}

// ---------------- launch ----------------
extern "C" void kernel_launch(void* const* d_in, const int* in_sizes, int n_in,
                              void* d_out, int out_size) {
    Ptrs ptrs;
    for (int i = 0; i < 32; i++) ptrs.p[i] = (const float*)d_in[i];
    const float* depth = (const float*)d_in[0];
    const float* sem   = (const float*)d_in[1];
    float* out = (float*)d_out;

    cudaFuncSetAttribute(moe_kernel, cudaFuncAttributeMaxDynamicSharedMemorySize, SMEM_TOTAL);

    pack_kernel<<<1, 256>>>(ptrs);
    semprob_kernel<<<NPIX / 4 / 256, 256>>>(sem, depth);
    finalize_kernel<<<1, 32>>>();
    moe_kernel<<<NPATCH / PPB, TPB, SMEM_TOTAL>>>(depth, out);
    tail_kernel<<<1, 32>>>(out);
}

// round 3
// speedup vs baseline: 1.2241x; 1.0029x over previous
#include <cuda_runtime.h>
#include <math.h>

// ---------------- problem constants ----------------
#define HH 480
#define WW2 480
#define HXW (HH*WW2)            // 230400
#define BATCH 8
#define NPIX (BATCH*HXW)        // 1843200
#define NCH 19
#define GRID_P 160
#define NPATCH (BATCH*GRID_P*GRID_P)   // 204800
#define PPB 64                  // patches per block (2 per thread)
#define TPB 288                 // threads
#define NROWS (PPB*9)           // 576 token rows
#define KSTR 20                 // row stride floats (80B, 16B aligned)

typedef unsigned long long ull;

// ---------------- f32x2 helpers ----------------
__device__ __forceinline__ ull dup2(float a) {
    ull r; asm("mov.b64 %0, {%1,%1};" : "=l"(r) : "f"(a)); return r;
}
__device__ __forceinline__ void upk2(ull v, float& a, float& b) {
    asm("mov.b64 {%0,%1}, %2;" : "=f"(a), "=f"(b) : "l"(v));
}
__device__ __forceinline__ ull fma2(ull a, ull b, ull c) {
    ull d; asm("fma.rn.f32x2 %0, %1, %2, %3;" : "=l"(d) : "l"(a), "l"(b), "l"(c)); return d;
}

// ---------------- device scratch ----------------
__device__ float  g_semprob[NPIX];
__device__ double g_acc[BATCH][4];
__device__ double g_gate_acc[3];
__device__ float4 g_norm[BATCH];

// ---------------- packed weights ----------------
struct SW {
    float in_w[768];  float in_b[48];
    float out_w[256]; float out_b[16];
    float eg1[256]; float es1[256]; float ef1[256];
    float eg2[256]; float es2[256]; float ef2[256];
    float Ag[16]; float Bg[16]; float Cg[16];
    float As[16]; float Bs[16]; float Cs[16];
    float Af[16]; float Bf[16]; float Cf[16];
    float b2g[16]; float b2s[16]; float b2f[16];
    float gw1t[768]; float gb1[16]; float gw2[48]; float gb2[4];
    float pw[16];   float pb[4];
    float dpw[16]; float dpb[16]; float spw[16]; float spb[16];
    float ebsum[16];
    float n1g[16]; float n1b[16]; float n2g[16]; float n2b[16];
};
#define NWFLOATS ((int)(sizeof(SW)/4))
__device__ float g_wblob[sizeof(SW)/4];

struct Ptrs { const float* p[32]; };

// dynamic smem layout
#define SW_BYTES ((int)sizeof(SW))
#define SK_OFF   SW_BYTES
#define SROW_B   (NROWS*KSTR*4)               // 46080
#define SV_OFF   (SK_OFF + SROW_B)
#define SST_OFF  SV_OFF                       // overlay: [64][48]
#define SHID_OFF (SV_OFF + 64*48*4)           // [64][16]
#define SGATE_OFF (SV_OFF + SROW_B)
#define SMEM_TOTAL (SGATE_OFF + 32)

// ---------------- pack weights ----------------
__global__ void pack_kernel(Ptrs in) {
    SW* w = (SW*)g_wblob;
    const int tid = threadIdx.x, nt = blockDim.x;
#define CP(dst, idx, n) for (int i = tid; i < (n); i += nt) (dst)[i] = in.p[idx][i];
    CP(w->in_w, 6, 768)  CP(w->in_b, 7, 48)
    CP(w->out_w, 8, 256) CP(w->out_b, 9, 16)
    CP(w->eg1, 12, 256)  CP(w->es1, 16, 256) CP(w->ef1, 20, 256)
    CP(w->eg2, 14, 256)  CP(w->es2, 18, 256) CP(w->ef2, 22, 256)
    CP(w->b2g, 15, 16)   CP(w->b2s, 19, 16)  CP(w->b2f, 23, 16)
    CP(w->gb1, 27, 16)   CP(w->gw2, 28, 48)  CP(w->pw, 30, 16)
    CP(w->dpw, 2, 16) CP(w->dpb, 3, 16) CP(w->spw, 4, 16) CP(w->spb, 5, 16)
    CP(w->n1g, 10, 16) CP(w->n1b, 11, 16) CP(w->n2g, 24, 16) CP(w->n2b, 25, 16)
#undef CP
    for (int i = tid; i < 768; i += nt) {         // g_w1 [48,16] -> gw1t [16][48]
        int r = i / 48, s = i - r * 48;
        w->gw1t[i] = in.p[26][s * 16 + r];
    }
    if (tid < 16) {                               // expert rank-1 folds
        const int j = tid;
        float ag = 0, cg = 0, bs = 0, cs = 0, af = 0, bf = 0, cf = 0;
        for (int k = 0; k < 16; k++) {
            const float eg = in.p[12][k*16 + j], es = in.p[16][k*16 + j], ef = in.p[20][k*16 + j];
            const float dpwk = in.p[2][k], dpbk = in.p[3][k];
            const float spwk = in.p[4][k], spbk = in.p[5][k];
            ag += dpwk * eg;  cg += dpbk * eg;
            bs += spwk * es;  cs += spbk * es;
            af += dpwk * ef;  bf += spwk * ef;
            cf += (dpbk + spbk) * ef;
        }
        w->Ag[j] = ag; w->Bg[j] = 0.f; w->Cg[j] = cg + in.p[13][j];
        w->As[j] = 0.f; w->Bs[j] = bs; w->Cs[j] = cs + in.p[17][j];
        w->Af[j] = af; w->Bf[j] = bf; w->Cf[j] = cf + in.p[21][j];
        w->ebsum[j] = in.p[3][j] + in.p[5][j];
    }
    if (tid < 3) w->gb2[tid] = in.p[29][tid];
    if (tid == 3) w->gb2[3] = 0.f;
    if (tid == 0) w->pb[0] = in.p[31][0];
    if (tid < BATCH*4) ((double*)g_acc)[tid] = 0.0;
    if (tid < 3) g_gate_acc[tid] = 0.0;
}

// ---------------- stage 1 ----------------
__global__ void semprob_kernel(const float* __restrict__ sem,
                               const float* __restrict__ depth) {
    const int q = blockIdx.x * 256 + threadIdx.x;
    const int p4 = q * 4;
    const int b = p4 / HXW;
    const int ip = p4 - b * HXW;
    const float4* base = (const float4*)(sem + (long)b * NCH * HXW + ip);
    float4 v[NCH];
#pragma unroll
    for (int c = 0; c < NCH; c++) v[c] = __ldg(base + (long)c * (HXW/4));
    float4 mx = v[0];
#pragma unroll
    for (int c = 1; c < NCH; c++) {
        mx.x = fmaxf(mx.x, v[c].x); mx.y = fmaxf(mx.y, v[c].y);
        mx.z = fmaxf(mx.z, v[c].z); mx.w = fmaxf(mx.w, v[c].w);
    }
    float4 sum = make_float4(0.f, 0.f, 0.f, 0.f);
#pragma unroll
    for (int c = 0; c < NCH; c++) {
        sum.x += __expf(v[c].x - mx.x); sum.y += __expf(v[c].y - mx.y);
        sum.z += __expf(v[c].z - mx.z); sum.w += __expf(v[c].w - mx.w);
    }
    float4 prob;
    prob.x = __fdividef(1.0f, sum.x); prob.y = __fdividef(1.0f, sum.y);
    prob.z = __fdividef(1.0f, sum.z); prob.w = __fdividef(1.0f, sum.w);
    ((float4*)g_semprob)[q] = prob;
    const float4 d = __ldg((const float4*)depth + q);

    double rd  = (double)d.x + (double)d.y + (double)d.z + (double)d.w;
    double rd2 = (double)d.x*d.x + (double)d.y*d.y + (double)d.z*d.z + (double)d.w*d.w;
    double rs  = (double)prob.x + (double)prob.y + (double)prob.z + (double)prob.w;
    double rs2 = (double)prob.x*prob.x + (double)prob.y*prob.y
               + (double)prob.z*prob.z + (double)prob.w*prob.w;
#pragma unroll
    for (int off = 16; off > 0; off >>= 1) {
        rd  += __shfl_down_sync(0xffffffffu, rd,  off);
        rd2 += __shfl_down_sync(0xffffffffu, rd2, off);
        rs  += __shfl_down_sync(0xffffffffu, rs,  off);
        rs2 += __shfl_down_sync(0xffffffffu, rs2, off);
    }
    __shared__ double sp[8][4];
    const int lane = threadIdx.x & 31, wid = threadIdx.x >> 5;
    if (lane == 0) { sp[wid][0] = rd; sp[wid][1] = rd2; sp[wid][2] = rs; sp[wid][3] = rs2; }
    __syncthreads();
    if (threadIdx.x == 0) {
        double a0 = 0, a1 = 0, a2 = 0, a3 = 0;
        for (int i = 0; i < 8; i++) { a0 += sp[i][0]; a1 += sp[i][1]; a2 += sp[i][2]; a3 += sp[i][3]; }
        atomicAdd(&g_acc[b][0], a0); atomicAdd(&g_acc[b][1], a1);
        atomicAdd(&g_acc[b][2], a2); atomicAdd(&g_acc[b][3], a3);
    }
}

__global__ void finalize_kernel() {
    const int b = threadIdx.x;
    if (b < BATCH) {
        const double n = (double)HXW;
        double md = g_acc[b][0] / n;
        double vd = (g_acc[b][1] - n * md * md) / (n - 1.0);
        double ms = g_acc[b][2] / n;
        double vs = (g_acc[b][3] - n * ms * ms) / (n - 1.0);
        g_norm[b] = make_float4((float)md, (float)(1.0 / (sqrt(vd) + 1e-6)),
                                (float)ms, (float)(1.0 / (sqrt(vs) + 1e-6)));
    }
}

// ---------------- helpers ----------------
__device__ __forceinline__ void ln16(float* x, const float* g, const float* b) {
    float m = 0.f;
#pragma unroll
    for (int j = 0; j < 16; j++) m += x[j];
    m *= 0.0625f;
    float v = 0.f;
#pragma unroll
    for (int j = 0; j < 16; j++) { float d = x[j] - m; v = fmaf(d, d, v); }
    v *= 0.0625f;
    const float r = rsqrtf(v + 1e-5f);
#pragma unroll
    for (int j = 0; j < 16; j++) x[j] = (x[j] - m) * r * g[j] + b[j];
}

__device__ __forceinline__ float gelu_fast(float x) {
    const float u = 0.70710678118654752f * x;
    const float a = fabsf(u);
    const float t = __fdividef(1.0f, fmaf(0.3275911f, a, 1.0f));
    float p =              1.061405429f;
    p = fmaf(p, t, -1.453152027f);
    p = fmaf(p, t,  1.421413741f);
    p = fmaf(p, t, -0.284496736f);
    p = fmaf(p, t,  0.254829592f);
    p = p * t;
    const float e = __expf(-u * u);
    float erf_u = 1.0f - p * e;
    erf_u = copysignf(erf_u, u);
    return 0.5f * x * (1.0f + erf_u);
}

// ---------------- stage 2 ----------------
__global__ void __launch_bounds__(TPB, 2)
moe_kernel(const float* __restrict__ depth, float* __restrict__ out) {
    extern __shared__ __align__(16) unsigned char dsm[];
    SW& w = *(SW*)dsm;
    float* s_k  = (float*)(dsm + SK_OFF);      // [576][KSTR]; later holds x rows
    float* s_v  = (float*)(dsm + SV_OFF);      // [576][KSTR]; later stats overlay
    float* s_st = (float*)(dsm + SST_OFF);     // [64][48]
    float* s_hid= (float*)(dsm + SHID_OFF);    // [64][16]
    double* s_gate = (double*)(dsm + SGATE_OFF);

    const int tid = threadIdx.x;
    for (int i = tid; i < NWFLOATS; i += TPB) ((float*)&w)[i] = g_wblob[i];
    if (tid < 3) s_gate[tid] = 0.0;
    __syncthreads();                                         // S0

    const int pl = tid / 9;
    const int t = tid - pl * 9;
    const int pbrow = tid - t;                 // = pl*9
    const int rowA = tid, rowB = tid + 288;

    float dn_[2], sn_[2];
    int pix_[2];
#pragma unroll
    for (int tok = 0; tok < 2; tok++) {
        const int P = blockIdx.x * PPB + pl + tok * 32;
        const int b = P / (GRID_P * GRID_P);
        const int rem = P - b * (GRID_P * GRID_P);
        const int hh = rem / GRID_P, ww = rem - hh * GRID_P;
        const int py = hh * 3 + t / 3, px = ww * 3 + (t % 3);
        const int pix = (b * HH + py) * WW2 + px;
        pix_[tok] = pix;
        const float4 nm = g_norm[b];
        dn_[tok] = (depth[pix] - nm.x) * nm.y;
        sn_[tok] = (g_semprob[pix] - nm.z) * nm.w;
    }

    // ---- embed + LN ----
    float x_[2][16];
#pragma unroll
    for (int tok = 0; tok < 2; tok++) {
        const ull dnd = dup2(dn_[tok]), snd = dup2(sn_[tok]);
        const ull *dw = (const ull*)w.dpw, *sw = (const ull*)w.spw, *eb = (const ull*)w.ebsum;
#pragma unroll
        for (int p = 0; p < 8; p++) {
            const ull v = fma2(dnd, dw[p], fma2(snd, sw[p], eb[p]));
            upk2(v, x_[tok][2*p], x_[tok][2*p+1]);
        }
        ln16(x_[tok], w.n1g, w.n1b);
    }

    // ---- qkv: K pass, V pass, Q pass (weights amortized over 2 tokens) ----
#define MMPASS(OFF, D0, D1) {                                            \
        const ull* bp = (const ull*)&w.in_b[OFF];                        \
        _Pragma("unroll") for (int p = 0; p < 8; p++) { D0[p] = bp[p]; D1[p] = bp[p]; } \
        _Pragma("unroll") for (int k = 0; k < 16; k++) {                 \
            const ull* r = (const ull*)&w.in_w[k*48 + OFF];              \
            const ull xv0 = dup2(x_[0][k]), xv1 = dup2(x_[1][k]);        \
            _Pragma("unroll") for (int p = 0; p < 8; p++) {              \
                D0[p] = fma2(xv0, r[p], D0[p]);                          \
                D1[p] = fma2(xv1, r[p], D1[p]); } } }

    ull q_[2][8];
    {
        ull a0[8], a1[8];
        MMPASS(16, a0, a1)
        ull* k0 = (ull*)&s_k[rowA * KSTR]; ull* k1 = (ull*)&s_k[rowB * KSTR];
#pragma unroll
        for (int p = 0; p < 8; p++) { k0[p] = a0[p]; k1[p] = a1[p]; }
        MMPASS(32, a0, a1)
        ull* v0 = (ull*)&s_v[rowA * KSTR]; ull* v1 = (ull*)&s_v[rowB * KSTR];
#pragma unroll
        for (int p = 0; p < 8; p++) { v0[p] = a0[p]; v1[p] = a1[p]; }
        MMPASS(0, q_[0], q_[1])
    }
    __syncthreads();                                         // S1

    // ---- attention ----
    float ao_[2][16];
#pragma unroll
    for (int tok = 0; tok < 2; tok++) {
        const int rb = pbrow + tok * 288;
#pragma unroll
        for (int h = 0; h < 2; h++) {
            float sc[9]; float mx = -1e30f;
#pragma unroll
            for (int tt = 0; tt < 9; tt++) {
                const ull* kr = (const ull*)&s_k[(rb + tt) * KSTR + h*8];
                ull a = 0ull;
#pragma unroll
                for (int p = 0; p < 4; p++) a = fma2(q_[tok][h*4 + p], kr[p], a);
                float a0, a1; upk2(a, a0, a1);
                const float s = (a0 + a1) * 0.35355339059327373f;
                sc[tt] = s; mx = fmaxf(mx, s);
            }
            float sum = 0.f;
#pragma unroll
            for (int tt = 0; tt < 9; tt++) { sc[tt] = __expf(sc[tt] - mx); sum += sc[tt]; }
            const float inv = __fdividef(1.0f, sum);
            ull vacc[4] = {0ull, 0ull, 0ull, 0ull};
#pragma unroll
            for (int tt = 0; tt < 9; tt++) {
                const ull s2 = dup2(sc[tt]);
                const ull* vr = (const ull*)&s_v[(rb + tt) * KSTR + h*8];
#pragma unroll
                for (int p = 0; p < 4; p++) vacc[p] = fma2(s2, vr[p], vacc[p]);
            }
#pragma unroll
            for (int p = 0; p < 4; p++) {
                float a0, a1; upk2(vacc[p], a0, a1);
                ao_[tok][h*8 + 2*p] = a0 * inv; ao_[tok][h*8 + 2*p + 1] = a1 * inv;
            }
        }
    }
    __syncthreads();                                         // S2 (attn reads done)

    // ---- out projection (joint) + residual + LN ----
    {
        ull a0[8], a1[8];
        const ull* bp = (const ull*)w.out_b;
#pragma unroll
        for (int p = 0; p < 8; p++) { a0[p] = bp[p]; a1[p] = bp[p]; }
#pragma unroll
        for (int k = 0; k < 16; k++) {
            const ull* r = (const ull*)&w.out_w[k*16];
            const ull v0 = dup2(ao_[0][k]), v1 = dup2(ao_[1][k]);
#pragma unroll
            for (int p = 0; p < 8; p++) { a0[p] = fma2(v0, r[p], a0[p]); a1[p] = fma2(v1, r[p], a1[p]); }
        }
#pragma unroll
        for (int p = 0; p < 8; p++) {
            float f0, f1; upk2(a0[p], f0, f1);
            x_[0][2*p] += f0; x_[0][2*p+1] += f1;
            upk2(a1[p], f0, f1);
            x_[1][2*p] += f0; x_[1][2*p+1] += f1;
        }
        ln16(x_[0], w.n1g, w.n1b);
        ln16(x_[1], w.n1g, w.n1b);
    }
    // store x rows (reuse s_k region)
    {
        ull* r0 = (ull*)&s_k[rowA * KSTR]; ull* r1 = (ull*)&s_k[rowB * KSTR];
        const ull* xa = (const ull*)x_[0]; const ull* xb = (const ull*)x_[1];
#pragma unroll
        for (int p = 0; p < 8; p++) { r0[p] = xa[p]; r1[p] = xb[p]; }
    }
    __syncthreads();                                         // S3
    float* s_x = s_k;

    // ---- gate stats (cooperative over channels) ----
#pragma unroll
    for (int tok = 0; tok < 2; tok++) {
        const int pp = pl + tok * 32;
        const int rb = pp * 9;
#pragma unroll
        for (int cc = 0; cc < 2; cc++) {
            const int c = (cc == 0) ? t : (9 + t);
            if (cc == 0 || t < 7) {
                float vals[9]; float m = 0.f, mxv = -1e30f;
#pragma unroll
                for (int tt = 0; tt < 9; tt++) {
                    const float v = s_x[(rb + tt) * KSTR + c];
                    vals[tt] = v; m += v; mxv = fmaxf(mxv, v);
                }
                m *= (1.0f / 9.0f);
                float var = 0.f;
#pragma unroll
                for (int tt = 0; tt < 9; tt++) { const float d = vals[tt] - m; var = fmaf(d, d, var); }
                const float sd = sqrtf(var * 0.125f);
                s_st[pp*48 + c] = m; s_st[pp*48 + 16 + c] = mxv; s_st[pp*48 + 32 + c] = sd;
            }
        }
    }
    __syncthreads();                                         // S4

    if (t < 8) {
#pragma unroll
        for (int tok = 0; tok < 2; tok++) {
            const int pp = pl + tok * 32;
            const ull* stp = (const ull*)&s_st[pp * 48];
#pragma unroll
            for (int cc = 0; cc < 2; cc++) {
                const int i = (cc == 0) ? t : (8 + t);
                const ull* wr = (const ull*)&w.gw1t[i * 48];
                ull a = 0ull;
#pragma unroll
                for (int p = 0; p < 24; p++) a = fma2(stp[p], wr[p], a);
                float a0, a1; upk2(a, a0, a1);
                s_hid[pp*16 + i] = gelu_fast(a0 + a1 + w.gb1[i]);
            }
        }
    }
    __syncthreads();                                         // S5

    float g_[2][3];
#pragma unroll
    for (int tok = 0; tok < 2; tok++) {
        const int pp = pl + tok * 32;
        const float* hv = &s_hid[pp * 16];
        float lg0 = w.gb2[0], lg1 = w.gb2[1], lg2 = w.gb2[2];
#pragma unroll
        for (int i = 0; i < 16; i++) {
            const float h = hv[i];
            lg0 = fmaf(h, w.gw2[i*3 + 0], lg0);
            lg1 = fmaf(h, w.gw2[i*3 + 1], lg1);
            lg2 = fmaf(h, w.gw2[i*3 + 2], lg2);
        }
        const float mxl = fmaxf(lg0, fmaxf(lg1, lg2));
        const float e0 = __expf(lg0 - mxl), e1 = __expf(lg1 - mxl), e2 = __expf(lg2 - mxl);
        const float inv = __fdividef(1.0f, e0 + e1 + e2);
        g_[tok][0] = e0 * inv; g_[tok][1] = e1 * inv; g_[tok][2] = e2 * inv;
    }
    if (t == 0) {
        atomicAdd(&s_gate[0], (double)g_[0][0] + (double)g_[1][0]);
        atomicAdd(&s_gate[1], (double)g_[0][1] + (double)g_[1][1]);
        atomicAdd(&s_gate[2], (double)g_[0][2] + (double)g_[1][2]);
    }

    // ---- experts (x read back from smem; weights amortized over 2 tokens) ----
    ull moe[2][8];
#pragma unroll
    for (int tok = 0; tok < 2; tok++) {
        const ull g0d = dup2(g_[tok][0]), g1d = dup2(g_[tok][1]), g2d = dup2(g_[tok][2]);
        const ull *bg = (const ull*)w.b2g, *bs = (const ull*)w.b2s, *bf = (const ull*)w.b2f;
#pragma unroll
        for (int p = 0; p < 8; p++)
            moe[tok][p] = fma2(g0d, bg[p], fma2(g1d, bs[p], fma2(g2d, bf[p], 0ull)));
    }

    const float* W1p[3] = {w.eg1, w.es1, w.ef1};
    const float* W2p[3] = {w.eg2, w.es2, w.ef2};
    const float* Ap[3]  = {w.Ag, w.As, w.Af};
    const float* Bp[3]  = {w.Bg, w.Bs, w.Bf};
    const float* Cp[3]  = {w.Cg, w.Cs, w.Cf};
    const int r0 = rowA * KSTR, r1 = rowB * KSTR;

#pragma unroll
    for (int e = 0; e < 3; e++) {
        ull h_[2][8];
#pragma unroll
        for (int tok = 0; tok < 2; tok++) {
            const ull dnd = dup2(dn_[tok]), snd = dup2(sn_[tok]);
            const ull *A = (const ull*)Ap[e], *B = (const ull*)Bp[e], *C = (const ull*)Cp[e];
#pragma unroll
            for (int p = 0; p < 8; p++) h_[tok][p] = fma2(dnd, A[p], fma2(snd, B[p], C[p]));
        }
#pragma unroll
        for (int k = 0; k < 16; k++) {
            const ull* wr = (const ull*)&W1p[e][k*16];
            const ull xv0 = dup2(s_x[r0 + k]), xv1 = dup2(s_x[r1 + k]);
#pragma unroll
            for (int p = 0; p < 8; p++) {
                h_[0][p] = fma2(xv0, wr[p], h_[0][p]);
                h_[1][p] = fma2(xv1, wr[p], h_[1][p]);
            }
        }
        float hf0[16], hf1[16];
#pragma unroll
        for (int p = 0; p < 8; p++) {
            float a, b;
            upk2(h_[0][p], a, b); hf0[2*p] = gelu_fast(a); hf0[2*p+1] = gelu_fast(b);
            upk2(h_[1][p], a, b); hf1[2*p] = gelu_fast(a); hf1[2*p+1] = gelu_fast(b);
        }
        ull a2[2][8];
#pragma unroll
        for (int p = 0; p < 8; p++) { a2[0][p] = 0ull; a2[1][p] = 0ull; }
#pragma unroll
        for (int k = 0; k < 16; k++) {
            const ull* wr = (const ull*)&W2p[e][k*16];
            const ull v0 = dup2(hf0[k]), v1 = dup2(hf1[k]);
#pragma unroll
            for (int p = 0; p < 8; p++) {
                a2[0][p] = fma2(v0, wr[p], a2[0][p]);
                a2[1][p] = fma2(v1, wr[p], a2[1][p]);
            }
        }
        const ull ge0 = dup2(g_[0][e]), ge1 = dup2(g_[1][e]);
#pragma unroll
        for (int p = 0; p < 8; p++) {
            moe[0][p] = fma2(ge0, a2[0][p], moe[0][p]);
            moe[1][p] = fma2(ge1, a2[1][p], moe[1][p]);
        }
    }

    // ---- final: residual folds + LN + project + sigmoid ----
#pragma unroll
    for (int tok = 0; tok < 2; tok++) {
        const int row = tok ? rowB : rowA;
        const ull* xr = (const ull*)&s_x[row * KSTR];
        const ull two = dup2(2.0f);
        const ull gdp = dup2(g_[tok][0] + g_[tok][2]);
        const ull gsp = dup2(g_[tok][1] + g_[tok][2]);
        const ull dnd = dup2(dn_[tok]), snd = dup2(sn_[tok]);
        const ull *dw = (const ull*)w.dpw, *db = (const ull*)w.dpb;
        const ull *sw = (const ull*)w.spw, *sb = (const ull*)w.spb;
        float mf[16];
#pragma unroll
        for (int p = 0; p < 8; p++) {
            ull v = fma2(two, xr[p], moe[tok][p]);
            const ull dpf = fma2(dnd, dw[p], db[p]);
            const ull spf = fma2(snd, sw[p], sb[p]);
            v = fma2(gdp, dpf, v);
            v = fma2(gsp, spf, v);
            upk2(v, mf[2*p], mf[2*p+1]);
        }
        ln16(mf, w.n2g, w.n2b);
        float z = w.pb[0];
#pragma unroll
        for (int j = 0; j < 16; j++) z = fmaf(mf[j], w.pw[j], z);
        out[pix_[tok]] = __fdividef(1.0f, 1.0f + __expf(-z));
    }

    __syncthreads();                                         // S6
    if (tid < 3) atomicAdd(&g_gate_acc[tid], s_gate[tid]);
}

__global__ void tail_kernel(float* __restrict__ out) {
    if (threadIdx.x < 3)
        out[NPIX + threadIdx.x] = (float)(g_gate_acc[threadIdx.x] / (double)NPATCH);
}

// ---------------- launch ----------------
extern "C" void kernel_launch(void* const* d_in, const int* in_sizes, int n_in,
                              void* d_out, int out_size) {
    Ptrs ptrs;
    for (int i = 0; i < 32; i++) ptrs.p[i] = (const float*)d_in[i];
    const float* depth = (const float*)d_in[0];
    const float* sem   = (const float*)d_in[1];
    float* out = (float*)d_out;

    cudaFuncSetAttribute(moe_kernel, cudaFuncAttributeMaxDynamicSharedMemorySize, SMEM_TOTAL);

    pack_kernel<<<1, 256>>>(ptrs);
    semprob_kernel<<<NPIX / 4 / 256, 256>>>(sem, depth);
    finalize_kernel<<<1, 32>>>();
    moe_kernel<<<NPATCH / PPB, TPB, SMEM_TOTAL>>>(depth, out);
    tail_kernel<<<1, 32>>>(out);
}